// round 14
// baseline (speedup 1.0000x reference)
#include <cuda_runtime.h>
#include <cuda_bf16.h>
#include <cstdint>

#define NEG_INF (-1e10f)
#define INVLN2 1.4426950408889634f
#define LN2    0.6931471805599453f

// Problem constants
#define BB 32
#define TT 1000
#define HH 512
#define VV 2048
#define LL 100
#define SS 201
#define MROWS (BB*TT)          // 32000
#define MPAD  (MROWS + 64)     // padding for DP prefetch overrun

// fp8 scaling: X*4, W*16 -> logits scaled by 64; descale in epilogue
#define XSCALE 4.0f
#define WSCALE 16.0f
#define DESCALE (1.0f / 64.0f)

// gemm tiling
#define G8_ROW    40                    // u16 per SMEM row (32 data + 8 pad)
#define G8_TILE_B (128 * G8_ROW * 2)    // 10240 bytes per tile per buffer
#define G8_BUFS   4
#define G8_SMEM   (G8_BUFS * G8_TILE_B * 2)   // A + B rings = 81920 B

// ---------------- static device scratch (no allocation allowed) ----------------
__device__ __align__(16) static unsigned short g_X8[MROWS * HH / 2];     // eouts e4m3 pairs (*4)
__device__ __align__(16) static unsigned short g_W8[VV * HH / 2];        // W e4m3 pairs (*16)
__device__ __align__(16) static unsigned short g_Wlab8[BB * 128 * HH / 2]; // gathered label W e4m3 (*16)
__device__ __align__(16) static float          g_blab[BB * 128];         // gathered label bias
__device__ __align__(16) static float          g_sumexp[MPAD];           // per-row sum(exp(logit))
__device__ __align__(16) static float          g_lab[(size_t)MPAD * 128];// (logit+blab)/ln2 (no lse)
__device__                static int           g_done[BB * 8];           // gemm1 tile flags
__device__                static int           g_cnt[256];               // gemm0 per-mtile counters

// ---------------- helpers ----------------
__device__ __forceinline__ unsigned smem_u32(const void* p) {
    return (unsigned)__cvta_generic_to_shared(p);
}

#define CP_ASYNC16(dst, src) \
    asm volatile("cp.async.ca.shared.global [%0], [%1], 16;\n" :: "r"(dst), "l"(src) : "memory")
#define CP_COMMIT() asm volatile("cp.async.commit_group;\n" ::: "memory")
#define CP_WAIT1()  asm volatile("cp.async.wait_group 1;\n" ::: "memory")
#define CP_WAIT2()  asm volatile("cp.async.wait_group 2;\n" ::: "memory")

__device__ __forceinline__ void ldmatrix_x4(unsigned* r, unsigned addr) {
    asm volatile("ldmatrix.sync.aligned.m8n8.x4.shared.b16 {%0,%1,%2,%3}, [%4];\n"
                 : "=r"(r[0]), "=r"(r[1]), "=r"(r[2]), "=r"(r[3]) : "r"(addr));
}

__device__ __forceinline__ void mma_fp8(float* d, const unsigned* a, unsigned b0, unsigned b1) {
    asm volatile("mma.sync.aligned.m16n8k32.row.col.f32.e4m3.e4m3.f32 "
                 "{%0,%1,%2,%3}, {%4,%5,%6,%7}, {%8,%9}, {%0,%1,%2,%3};\n"
                 : "+f"(d[0]), "+f"(d[1]), "+f"(d[2]), "+f"(d[3])
                 : "r"(a[0]), "r"(a[1]), "r"(a[2]), "r"(a[3]), "r"(b0), "r"(b1));
}

__device__ __forceinline__ float ex2f(float x) {
    float y; asm("ex2.approx.f32 %0, %1;" : "=f"(y) : "f"(x)); return y;
}
__device__ __forceinline__ float lg2f(float x) {
    float y; asm("lg2.approx.f32 %0, %1;" : "=f"(y) : "f"(x)); return y;
}

__device__ __forceinline__ unsigned short fp8pack(float lo, float hi) {
    unsigned short h;
    asm("cvt.rn.satfinite.e4m3x2.f32 %0, %1, %2;" : "=h"(h) : "f"(hi), "f"(lo));
    return h;
}

__device__ __forceinline__ unsigned pack8(float4 u, float4 v, float s, int sel) {
    unsigned short h0, h1;
    if (sel == 0) { h0 = fp8pack(u.x * s, u.y * s); h1 = fp8pack(u.z * s, u.w * s); }
    else          { h0 = fp8pack(v.x * s, v.y * s); h1 = fp8pack(v.z * s, v.w * s); }
    return (unsigned)h0 | ((unsigned)h1 << 16);
}

// ---------------- kernel 1: convert + gather + zero scratch/out ----------------
__global__ void prep_kernel(const float* __restrict__ eouts, const float* __restrict__ W,
                            const float* __restrict__ bias, const int* __restrict__ ys,
                            const int* __restrict__ elens,
                            float* __restrict__ out, int out_size) {
    int i = blockIdx.x * blockDim.x + threadIdx.x;
    int stride = gridDim.x * blockDim.x;
    for (int k = i; k < MROWS * HH / 8; k += stride) {
        int row = k >> 6;
        int b   = row / TT;
        int t   = row - b * TT;
        if (t < elens[b]) {
            float4 u = ((const float4*)eouts)[2 * k];
            float4 v = ((const float4*)eouts)[2 * k + 1];
            uint2 o;
            o.x = pack8(u, v, XSCALE, 0);
            o.y = pack8(u, v, XSCALE, 1);
            ((uint2*)g_X8)[k] = o;
        }
    }
    for (int k = i; k < VV * HH / 8; k += stride) {
        float4 u = ((const float4*)W)[2 * k];
        float4 v = ((const float4*)W)[2 * k + 1];
        uint2 o;
        o.x = pack8(u, v, WSCALE, 0);
        o.y = pack8(u, v, WSCALE, 1);
        ((uint2*)g_W8)[k] = o;
    }
    for (int k = i; k < BB * 128 * HH / 2; k += stride) {
        int kk2 = k & 255;
        int j   = (k >> 8) & 127;
        int b   = k >> 15;
        int v   = (j == 0) ? 0 : ((j <= LL) ? ys[b * LL + (j - 1)] : -1);
        if (v >= 0) {
            float2 ww = ((const float2*)(W + (size_t)v * HH))[kk2];
            g_Wlab8[k] = fp8pack(ww.x * WSCALE, ww.y * WSCALE);
        } else {
            g_Wlab8[k] = 0;
        }
    }
    for (int k = i; k < BB * 128; k += stride) {
        int j = k & 127;
        int b = k >> 7;
        int v = (j == 0) ? 0 : ((j <= LL) ? ys[b * LL + (j - 1)] : -1);
        g_blab[k] = (v >= 0) ? bias[v] : 0.0f;
    }
    for (int k = i; k < MPAD; k += stride) g_sumexp[k] = 0.0f;
    for (int k = i; k < BB * 8; k += stride) g_done[k] = 0;
    for (int k = i; k < 256; k += stride) g_cnt[k] = 0;
    for (int k = i; k < out_size; k += stride) out[k] = 0.0f;
}

// ---------------- kernel 2: FUSED gemm0 + gemm1 + CTC DP ----------------
// grid 4288, block 288:
//   blocks [0,32):     DP role, batch = blockIdx
//   blocks [32,288):   label GEMM tiles (bx = flat>>5 frame tile, by = flat&31 batch)
//   blocks [288,4288): full-V GEMM (rank = idx-288; nc = rank&15, m-tile = rank>>4)
// gemm1 publishes g_done[by*8+bx]; gemm0 publishes g_cnt[m] (16 => mtile sumexp ready).
// DP (tid0 spin + nanosleep) waits on both; producers never wait => deadlock-free.
__global__ __launch_bounds__(288, 2)
void fused_kernel(const float* __restrict__ bias, const int* __restrict__ ys,
                  const int* __restrict__ elens, const int* __restrict__ ylens,
                  float* __restrict__ out) {
    extern __shared__ char smraw[];
    const int tid = threadIdx.x;

    if (blockIdx.x >= 288) {
        // ================= full-V GEMM role =================
        const int rank = blockIdx.x - 288;
        const int by = rank & 15;          // n-chunk
        const int bx = rank >> 4;          // m-tile 0..249
        {
            int r0 = bx * 128;
            int b0 = r0 / 1000;
            int b1 = (r0 + 127) / 1000;
            if (b0 == b1 && (r0 - b0 * 1000) >= elens[b0]) {
                if (tid == 0) atomicAdd(&g_cnt[bx], 1);
                return;
            }
        }

        const unsigned As0 = smem_u32(smraw);
        const unsigned Bs0 = As0 + G8_BUFS * G8_TILE_B;
        const bool act = (tid < 256);
        const int lane = tid & 31, wid = tid >> 5;
        const int wm = (wid & 3) * 32;
        const int wn = (wid >> 2) * 64;

        const int ldrow = (tid >> 1) & 127;
        const int ccol  = (tid & 1) * 16;
        const unsigned short* Ag = g_X8 + (size_t)(bx * 128 + ldrow) * 256 + ccol;
        const unsigned short* Bg = g_W8 + (size_t)(by * 128 + ldrow) * 256 + ccol;
        const unsigned soff = (unsigned)(ldrow * G8_ROW + ccol) * 2;

        auto stage = [&](int kt) {
            if (act) {
                const unsigned bo = (unsigned)(kt & 3) * G8_TILE_B;
                const unsigned short* sa = Ag + kt * 32;
                const unsigned short* sb = Bg + kt * 32;
                CP_ASYNC16(As0 + bo + soff,      sa);
                CP_ASYNC16(As0 + bo + soff + 16, sa + 8);
                CP_ASYNC16(Bs0 + bo + soff,      sb);
                CP_ASYNC16(Bs0 + bo + soff + 16, sb + 8);
                CP_COMMIT();
            }
        };

        float d[2][8][4];
#pragma unroll
        for (int mi = 0; mi < 2; mi++)
#pragma unroll
            for (int nj = 0; nj < 8; nj++)
#pragma unroll
                for (int q = 0; q < 4; q++) d[mi][nj][q] = 0.0f;

        unsigned aAddr[2], bAddr[4];
#pragma unroll
        for (int mi = 0; mi < 2; mi++)
            aAddr[mi] = As0 + (unsigned)((wm + mi * 16 + (lane & 15)) * G8_ROW + (lane >> 4) * 8) * 2;
#pragma unroll
        for (int np = 0; np < 4; np++) {
            int r = wn + np * 16 + (lane & 7) + ((lane >> 4) & 1) * 8;
            int c = ((lane >> 3) & 1) * 8;
            bAddr[np] = Bs0 + (unsigned)(r * G8_ROW + c) * 2;
        }

        stage(0); stage(1); stage(2);

#pragma unroll
        for (int kt = 0; kt < 8; kt++) {
            CP_WAIT2();
            __syncthreads();
            if (act) {
                const unsigned bo = (unsigned)(kt & 3) * G8_TILE_B;
#pragma unroll
                for (int kq = 0; kq < 2; kq++) {
                    const unsigned off = bo + kq * 32;
                    unsigned ra[2][4], rb[4][4];
#pragma unroll
                    for (int mi = 0; mi < 2; mi++) ldmatrix_x4(ra[mi], aAddr[mi] + off);
#pragma unroll
                    for (int np = 0; np < 4; np++) ldmatrix_x4(rb[np], bAddr[np] + off);
#pragma unroll
                    for (int mi = 0; mi < 2; mi++)
#pragma unroll
                        for (int nj = 0; nj < 8; nj++) {
                            int np = nj >> 1;
                            unsigned b0 = (nj & 1) ? rb[np][2] : rb[np][0];
                            unsigned b1 = (nj & 1) ? rb[np][3] : rb[np][1];
                            mma_fp8(d[mi][nj], ra[mi], b0, b1);
                        }
                }
            }
            if (kt + 3 < 8) stage(kt + 3); else if (act) CP_COMMIT();
        }

        if (act) {
            const float dsc = INVLN2 * DESCALE;
#pragma unroll
            for (int mi = 0; mi < 2; mi++) {
                float se0 = 0.0f, se1 = 0.0f;
                int r = bx * 128 + wm + mi * 16 + (lane >> 2);
#pragma unroll
                for (int nj = 0; nj < 8; nj++) {
                    int c = by * 128 + wn + nj * 8 + (lane & 3) * 2;
                    float b0 = __ldg(&bias[c]) * INVLN2;
                    float b1 = __ldg(&bias[c + 1]) * INVLN2;
                    se0 += ex2f(fmaf(d[mi][nj][0], dsc, b0)) + ex2f(fmaf(d[mi][nj][1], dsc, b1));
                    se1 += ex2f(fmaf(d[mi][nj][2], dsc, b0)) + ex2f(fmaf(d[mi][nj][3], dsc, b1));
                }
                se0 += __shfl_xor_sync(0xffffffffu, se0, 1);
                se0 += __shfl_xor_sync(0xffffffffu, se0, 2);
                se1 += __shfl_xor_sync(0xffffffffu, se1, 1);
                se1 += __shfl_xor_sync(0xffffffffu, se1, 2);
                if ((lane & 3) == 0) {
                    atomicAdd(&g_sumexp[r], se0);
                    atomicAdd(&g_sumexp[r + 8], se1);
                }
            }
        }
        __threadfence();
        __syncthreads();
        if (tid == 0) atomicAdd(&g_cnt[bx], 1);
        return;
    }

    if (blockIdx.x >= 32) {
        // ================= label GEMM role (no lse; no gemm0 dependency) =================
        const int flat = blockIdx.x - 32;
        const int bx = flat >> 5;
        const int by = flat & 31;

        if (bx * 128 >= elens[by]) {
            if (tid == 0) { __threadfence(); atomicExch(&g_done[by * 8 + bx], 1); }
            return;
        }

        const unsigned As0 = smem_u32(smraw);
        const unsigned Bs0 = As0 + G8_BUFS * G8_TILE_B;
        const bool act = (tid < 256);
        const int lane = tid & 31, wid = tid >> 5;
        const int wm = (wid & 3) * 32;
        const int wn = (wid >> 2) * 64;

        const int ldrow = (tid >> 1) & 127;
        const int ccol  = (tid & 1) * 16;
        int trow_ld = bx * 128 + ldrow;
        if (trow_ld > TT - 1) trow_ld = TT - 1;
        const unsigned short* Ag = g_X8    + (size_t)(by * TT + trow_ld) * 256 + ccol;
        const unsigned short* Bg = g_Wlab8 + (size_t)(by * 128 + ldrow) * 256 + ccol;
        const unsigned soff = (unsigned)(ldrow * G8_ROW + ccol) * 2;

        auto stage = [&](int kt) {
            if (act) {
                const unsigned bo = (unsigned)(kt & 3) * G8_TILE_B;
                const unsigned short* sa = Ag + kt * 32;
                const unsigned short* sb = Bg + kt * 32;
                CP_ASYNC16(As0 + bo + soff,      sa);
                CP_ASYNC16(As0 + bo + soff + 16, sa + 8);
                CP_ASYNC16(Bs0 + bo + soff,      sb);
                CP_ASYNC16(Bs0 + bo + soff + 16, sb + 8);
                CP_COMMIT();
            }
        };

        float d[2][8][4];
#pragma unroll
        for (int mi = 0; mi < 2; mi++)
#pragma unroll
            for (int nj = 0; nj < 8; nj++)
#pragma unroll
                for (int q = 0; q < 4; q++) d[mi][nj][q] = 0.0f;

        unsigned aAddr[2], bAddr[4];
#pragma unroll
        for (int mi = 0; mi < 2; mi++)
            aAddr[mi] = As0 + (unsigned)((wm + mi * 16 + (lane & 15)) * G8_ROW + (lane >> 4) * 8) * 2;
#pragma unroll
        for (int np = 0; np < 4; np++) {
            int r = wn + np * 16 + (lane & 7) + ((lane >> 4) & 1) * 8;
            int c = ((lane >> 3) & 1) * 8;
            bAddr[np] = Bs0 + (unsigned)(r * G8_ROW + c) * 2;
        }

        stage(0); stage(1); stage(2);

#pragma unroll
        for (int kt = 0; kt < 8; kt++) {
            CP_WAIT2();
            __syncthreads();
            if (act) {
                const unsigned bo = (unsigned)(kt & 3) * G8_TILE_B;
#pragma unroll
                for (int kq = 0; kq < 2; kq++) {
                    const unsigned off = bo + kq * 32;
                    unsigned ra[2][4], rb[4][4];
#pragma unroll
                    for (int mi = 0; mi < 2; mi++) ldmatrix_x4(ra[mi], aAddr[mi] + off);
#pragma unroll
                    for (int np = 0; np < 4; np++) ldmatrix_x4(rb[np], bAddr[np] + off);
#pragma unroll
                    for (int mi = 0; mi < 2; mi++)
#pragma unroll
                        for (int nj = 0; nj < 8; nj++) {
                            int np = nj >> 1;
                            unsigned b0 = (nj & 1) ? rb[np][2] : rb[np][0];
                            unsigned b1 = (nj & 1) ? rb[np][3] : rb[np][1];
                            mma_fp8(d[mi][nj], ra[mi], b0, b1);
                        }
                }
            }
            if (kt + 3 < 8) stage(kt + 3); else if (act) CP_COMMIT();
        }

        if (act) {
            // store lp2' = (d/64 + blab) / ln2    (lse applied by DP)
#pragma unroll
            for (int mi = 0; mi < 2; mi++) {
                int trow = bx * 128 + wm + mi * 16 + (lane >> 2);
#pragma unroll
                for (int nj = 0; nj < 8; nj++) {
                    int c = wn + nj * 8 + (lane & 3) * 2;
                    float bl0 = g_blab[by * 128 + c];
                    float bl1 = g_blab[by * 128 + c + 1];
                    if (trow < TT) {
                        float2 v = make_float2(
                            fmaf(d[mi][nj][0], DESCALE, bl0) * INVLN2,
                            fmaf(d[mi][nj][1], DESCALE, bl1) * INVLN2);
                        *(float2*)&g_lab[(size_t)(by * TT + trow) * 128 + c] = v;
                    }
                    if (trow + 8 < TT) {
                        float2 v = make_float2(
                            fmaf(d[mi][nj][2], DESCALE, bl0) * INVLN2,
                            fmaf(d[mi][nj][3], DESCALE, bl1) * INVLN2);
                        *(float2*)&g_lab[(size_t)(by * TT + trow + 8) * 128 + c] = v;
                    }
                }
            }
        }
        __threadfence();
        __syncthreads();
        if (tid == 0) atomicExch(&g_done[by * 8 + bx], 1);
        return;
    }

    // ================= CTC DP role =================
    const int b    = blockIdx.x;
    const int lane = tid & 31;
    const int w    = tid >> 5;              // 0..8
    const int s    = w * 24 + lane - 8;     // R8 trapezoid layout over 9 warps... (288 thr)

    float* Asd = (float*)smraw;                       // [2][220]
    float* qb  = (float*)(smraw + 1792);              // [2][24][128]
    float* lsb = (float*)(smraw + 1792 + 24576);      // [2][24]
    const unsigned qb0 = smem_u32(smraw) + 1792;

    const int ylen = ylens[b];
    const int tend = elens[b] - 1;

    const bool in_s  = (s >= 0 && s <= 200);
    const bool valid = in_s && (s <= 2 * ylen);

    const int sc0 = min(max(s, 0), 200);
    const int li0 = (sc0 & 1) ? ((sc0 >> 1) + 1) : 0;

    auto skip_of = [&](int x) -> float {
        if ((x & 1) && x >= 3 && x <= 200) {
            int h = x >> 1;
            return (ys[b * LL + h] != ys[b * LL + h - 1]) ? 1.0f : 0.0f;
        }
        return 0.0f;
    };
    const float sk0 = skip_of(s);
    const float sk1 = skip_of(s - 1);
    const float sk2 = skip_of(s - 2);
    const bool use3 = (sk0 != 0.0f) || (sk1 != 0.0f);
    const bool use4 = (sk0 != 0.0f) && (sk2 != 0.0f);

    // dependency waiter: tid0 spins (nanosleep backoff), block barriers after
    volatile int* dn1 = (volatile int*)(g_done + b * 8);
    volatile int* cnt = (volatile int*)g_cnt;
    int rdy1 = 0;
    int rdym = (b * TT) >> 7;
    auto waitDeps = [&](int tl) {
        if (tid == 0) {
            int tile1 = tl >> 7;
            int m0 = (b * TT + tl) >> 7;
            while (rdy1 <= tile1) { if (dn1[rdy1] != 0) rdy1++; else __nanosleep(128); }
            while (rdym <= m0)    { if (cnt[rdym] >= 16) rdym++; else __nanosleep(128); }
        }
        __syncthreads();
        __threadfence();
    };

    float pendA = 1.0f, pendB = 1.0f;

    auto stage = [&](int cc, int bf) {
        int t0 = 1 + cc * 24;
        int tl = min(t0 + 23, TT - 1);
        waitDeps(tl);
        const float4* src = (const float4*)(g_lab + (size_t)(b * TT + t0) * 128);
        unsigned dst = qb0 + (unsigned)bf * 12288u;
        for (int idx = tid; idx < 768; idx += 288)
            CP_ASYNC16(dst + (unsigned)idx * 16u, src + idx);
        CP_COMMIT();
        if (tid < 24) {
            float v = __ldcg(&g_sumexp[b * TT + t0 + tid]);   // .cg: L2-coherent
            if (bf) pendB = v; else pendA = v;
        }
    };

    // t = 0 init
    waitDeps(0);
    float ls0 = lg2f(__ldcg(&g_sumexp[b * TT]));
    float a = NEG_INF;
    if (valid && s < 2) a = g_lab[(size_t)(b * TT) * 128 + li0] - ls0;

    auto dstep = [&](int f0, int bf) {
        float a1 = __shfl_up_sync(0xffffffffu, a, 1);
        float a2 = __shfl_up_sync(0xffffffffu, a, 2);
        float a3 = __shfl_up_sync(0xffffffffu, a, 3);
        float a4 = __shfl_up_sync(0xffffffffu, a, 4);
        float a3u = use3 ? a3 : NEG_INF;
        float a4u = use4 ? a4 : NEG_INF;
        float lpA = qb[(bf * 24 + f0) * 128 + li0] - lsb[bf * 24 + f0];
        float lpB = qb[(bf * 24 + f0 + 1) * 128 + li0] - lsb[bf * 24 + f0 + 1];
        float P0 = ex2f(lpA);
        float P1 = __shfl_up_sync(0xffffffffu, P0, 1);
        float P2 = __shfl_up_sync(0xffffffffu, P0, 2);
        float m  = fmaxf(fmaxf(a, a1), fmaxf(fmaxf(a2, a3u), a4u));
        float q0 = ex2f(a - m),  q1 = ex2f(a1 - m), q2 = ex2f(a2 - m);
        float q3 = ex2f(a3u - m), q4 = ex2f(a4u - m);
        float I0 = fmaf(sk0, q2, q0 + q1);
        float I1 = fmaf(sk1, q3, q1 + q2);
        float I2 = fmaf(sk2, q4, q2 + q3);
        float S  = fmaf(P0, I0, fmaf(P1, I1, sk0 * P2 * I2));
        float nv = fmaxf(m + lg2f(S) + lpB, NEG_INF);
        a = valid ? nv : NEG_INF;
    };

    auto sstep = [&](int f0, int bf) {
        float a1 = __shfl_up_sync(0xffffffffu, a, 1);
        float a2 = __shfl_up_sync(0xffffffffu, a, 2);
        if (sk0 == 0.0f) a2 = NEG_INF;
        float lp = qb[(bf * 24 + f0) * 128 + li0] - lsb[bf * 24 + f0];
        float m  = fmaxf(a, fmaxf(a1, a2));
        float su = ex2f(a - m) + ex2f(a1 - m) + ex2f(a2 - m);
        float nv = fmaxf(m + lg2f(su) + lp, NEG_INF);
        a = valid ? nv : NEG_INF;
    };

    stage(0, 0);
    stage(1, 1);

    int wb = 0, lastwb = 0;
    int t = 1, c = 0;
    while (t <= tend) {
        CP_WAIT1();
        __syncthreads();
        const int bf = c & 1;
        if (tid < 24) lsb[bf * 24 + tid] = lg2f(bf ? pendB : pendA);
        __syncthreads();
        const int nfr = min(24, tend - t + 1);
        int fr = 0;
        while (fr < nfr) {
            int rem = nfr - fr;
            int h;
            if (rem >= 4)      { dstep(fr, bf); dstep(fr + 2, bf); h = 8; fr += 4; }
            else if (rem >= 2) { dstep(fr, bf);                    h = 4; fr += 2; }
            else               { sstep(fr, bf);                    h = 2; fr += 1; }
            if (lane >= h && in_s) Asd[wb * 220 + s] = a;
            __syncthreads();
            a = in_s ? Asd[wb * 220 + s] : NEG_INF;
            lastwb = wb; wb ^= 1;
        }
        if (nfr == 24) stage(c + 2, bf);
        t += nfr; c++;
    }

    if (tid == 0) {
        float last = Asd[lastwb * 220 + 2 * ylen];
        float prev = Asd[lastwb * 220 + 2 * ylen - 1];
        float mm = fmaxf(last, prev);
        float l2v = mm + lg2f(ex2f(last - mm) + ex2f(prev - mm));
        float lnat = -l2v * LN2;
        if (!(lnat < -0.5f * NEG_INF)) lnat = 0.0f;   // zero_infinity
        atomicAdd(out, lnat * (1.0f / (float)BB));
    }
}

// ---------------- launch ----------------
extern "C" void kernel_launch(void* const* d_in, const int* in_sizes, int n_in,
                              void* d_out, int out_size) {
    const float* eouts = (const float*)d_in[0];
    const float* W     = (const float*)d_in[1];
    const float* bias  = (const float*)d_in[2];
    const int*   ys    = (const int*)d_in[3];
    const int*   elens = (const int*)d_in[4];
    const int*   ylens = (const int*)d_in[5];
    float* out = (float*)d_out;

    cudaFuncSetAttribute(fused_kernel,
                         cudaFuncAttributeMaxDynamicSharedMemorySize, G8_SMEM);

    prep_kernel<<<2048, 256>>>(eouts, W, bias, ys, elens, out, out_size);
    fused_kernel<<<4288, 288, G8_SMEM>>>(bias, ys, elens, ylens, out);
}

// round 15
// speedup vs baseline: 1.3372x; 1.3372x over previous
#include <cuda_runtime.h>
#include <cuda_bf16.h>
#include <cstdint>

#define NEG_INF (-1e10f)
#define INVLN2 1.4426950408889634f
#define LN2    0.6931471805599453f

// Problem constants
#define BB 32
#define TT 1000
#define HH 512
#define VV 2048
#define LL 100
#define SS 201
#define MROWS (BB*TT)          // 32000
#define MPAD  (MROWS + 64)     // padding for DP prefetch overrun

// fp8 scaling: X*4, W*16 -> logits scaled by 64; descale in epilogue
#define XSCALE 4.0f
#define WSCALE 16.0f
#define DESCALE (1.0f / 64.0f)

// gemm tiling
#define G8_ROW    40                    // u16 per SMEM row (32 data + 8 pad)
#define G8_TILE_B (128 * G8_ROW * 2)    // 10240 bytes per tile per buffer
#define G8_BUFS   4
#define G8_SMEM   (G8_BUFS * G8_TILE_B * 2)   // A + B rings = 81920 B

// ---------------- static device scratch (no allocation allowed) ----------------
__device__ __align__(16) static unsigned short g_X8[MROWS * HH / 2];     // eouts e4m3 pairs (*4)
__device__ __align__(16) static unsigned short g_W8[VV * HH / 2];        // W e4m3 pairs (*16)
__device__ __align__(16) static unsigned short g_Wlab8[BB * 128 * HH / 2]; // gathered label W e4m3 (*16)
__device__ __align__(16) static float          g_blab[BB * 128];         // gathered label bias
__device__ __align__(16) static float          g_sumexp[MPAD];           // per-row sum(exp(logit))
__device__ __align__(16) static float          g_lab[(size_t)MPAD * 128];// (logit+blab)/ln2 (no lse)
__device__                static int           g_done[BB * 8];           // gemm1 tile flags
__device__                static int           g_cnt[256];               // gemm0 per-mtile counters

// ---------------- helpers ----------------
__device__ __forceinline__ unsigned smem_u32(const void* p) {
    return (unsigned)__cvta_generic_to_shared(p);
}

#define CP_ASYNC16(dst, src) \
    asm volatile("cp.async.ca.shared.global [%0], [%1], 16;\n" :: "r"(dst), "l"(src) : "memory")
#define CP_COMMIT() asm volatile("cp.async.commit_group;\n" ::: "memory")
#define CP_WAIT1()  asm volatile("cp.async.wait_group 1;\n" ::: "memory")
#define CP_WAIT2()  asm volatile("cp.async.wait_group 2;\n" ::: "memory")

__device__ __forceinline__ void ldmatrix_x4(unsigned* r, unsigned addr) {
    asm volatile("ldmatrix.sync.aligned.m8n8.x4.shared.b16 {%0,%1,%2,%3}, [%4];\n"
                 : "=r"(r[0]), "=r"(r[1]), "=r"(r[2]), "=r"(r[3]) : "r"(addr));
}

__device__ __forceinline__ void mma_fp8(float* d, const unsigned* a, unsigned b0, unsigned b1) {
    asm volatile("mma.sync.aligned.m16n8k32.row.col.f32.e4m3.e4m3.f32 "
                 "{%0,%1,%2,%3}, {%4,%5,%6,%7}, {%8,%9}, {%0,%1,%2,%3};\n"
                 : "+f"(d[0]), "+f"(d[1]), "+f"(d[2]), "+f"(d[3])
                 : "r"(a[0]), "r"(a[1]), "r"(a[2]), "r"(a[3]), "r"(b0), "r"(b1));
}

__device__ __forceinline__ float ex2f(float x) {
    float y; asm("ex2.approx.f32 %0, %1;" : "=f"(y) : "f"(x)); return y;
}
__device__ __forceinline__ float lg2f(float x) {
    float y; asm("lg2.approx.f32 %0, %1;" : "=f"(y) : "f"(x)); return y;
}

__device__ __forceinline__ unsigned short fp8pack(float lo, float hi) {
    unsigned short h;
    asm("cvt.rn.satfinite.e4m3x2.f32 %0, %1, %2;" : "=h"(h) : "f"(hi), "f"(lo));
    return h;
}

__device__ __forceinline__ unsigned pack8(float4 u, float4 v, float s, int sel) {
    unsigned short h0, h1;
    if (sel == 0) { h0 = fp8pack(u.x * s, u.y * s); h1 = fp8pack(u.z * s, u.w * s); }
    else          { h0 = fp8pack(v.x * s, v.y * s); h1 = fp8pack(v.z * s, v.w * s); }
    return (unsigned)h0 | ((unsigned)h1 << 16);
}

// ---------------- kernel 1: convert + gather + zero scratch/out ----------------
__global__ void prep_kernel(const float* __restrict__ eouts, const float* __restrict__ W,
                            const float* __restrict__ bias, const int* __restrict__ ys,
                            const int* __restrict__ elens,
                            float* __restrict__ out, int out_size) {
    int i = blockIdx.x * blockDim.x + threadIdx.x;
    int stride = gridDim.x * blockDim.x;
    for (int k = i; k < MROWS * HH / 8; k += stride) {
        int row = k >> 6;
        int b   = row / TT;
        int t   = row - b * TT;
        if (t < elens[b]) {
            float4 u = ((const float4*)eouts)[2 * k];
            float4 v = ((const float4*)eouts)[2 * k + 1];
            uint2 o;
            o.x = pack8(u, v, XSCALE, 0);
            o.y = pack8(u, v, XSCALE, 1);
            ((uint2*)g_X8)[k] = o;
        }
    }
    for (int k = i; k < VV * HH / 8; k += stride) {
        float4 u = ((const float4*)W)[2 * k];
        float4 v = ((const float4*)W)[2 * k + 1];
        uint2 o;
        o.x = pack8(u, v, WSCALE, 0);
        o.y = pack8(u, v, WSCALE, 1);
        ((uint2*)g_W8)[k] = o;
    }
    for (int k = i; k < BB * 128 * HH / 2; k += stride) {
        int kk2 = k & 255;
        int j   = (k >> 8) & 127;
        int b   = k >> 15;
        int v   = (j == 0) ? 0 : ((j <= LL) ? ys[b * LL + (j - 1)] : -1);
        if (v >= 0) {
            float2 ww = ((const float2*)(W + (size_t)v * HH))[kk2];
            g_Wlab8[k] = fp8pack(ww.x * WSCALE, ww.y * WSCALE);
        } else {
            g_Wlab8[k] = 0;
        }
    }
    for (int k = i; k < BB * 128; k += stride) {
        int j = k & 127;
        int b = k >> 7;
        int v = (j == 0) ? 0 : ((j <= LL) ? ys[b * LL + (j - 1)] : -1);
        g_blab[k] = (v >= 0) ? bias[v] : 0.0f;
    }
    for (int k = i; k < MPAD; k += stride) g_sumexp[k] = 0.0f;
    for (int k = i; k < BB * 8; k += stride) g_done[k] = 0;
    for (int k = i; k < 256; k += stride) g_cnt[k] = 0;
    for (int k = i; k < out_size; k += stride) out[k] = 0.0f;
}

// ---------------- kernel 2: FUSED gemm0 + gemm1 + CTC DP (256 thr, occ 2) ----------------
// grid 4288, block 256:
//   blocks [0,32):     DP role, batch = blockIdx
//   blocks [32,288):   label GEMM tiles (bx = flat>>5 frame tile, by = flat&31 batch)
//   blocks [288,4288): full-V GEMM (rank = idx-288; nc = rank&15, m-tile = rank>>4)
// gemm1 publishes g_done[by*8+bx]; gemm0 publishes g_cnt[m] (16 => mtile sumexp ready).
// DP (tid0 spin + nanosleep) waits on both; producers never wait => deadlock-free
// (wave 1 = 296 slots >= 32 DP + 256 gemm1 blocks).
__global__ __launch_bounds__(256, 2)
void fused_kernel(const float* __restrict__ bias, const int* __restrict__ ys,
                  const int* __restrict__ elens, const int* __restrict__ ylens,
                  float* __restrict__ out) {
    extern __shared__ char smraw[];
    const int tid = threadIdx.x;

    if (blockIdx.x >= 288) {
        // ================= full-V GEMM role =================
        const int rank = blockIdx.x - 288;
        const int by = rank & 15;          // n-chunk
        const int bx = rank >> 4;          // m-tile 0..249
        {
            int r0 = bx * 128;
            int b0 = r0 / 1000;
            int b1 = (r0 + 127) / 1000;
            if (b0 == b1 && (r0 - b0 * 1000) >= elens[b0]) {
                if (tid == 0) atomicAdd(&g_cnt[bx], 1);
                return;
            }
        }

        const unsigned As0 = smem_u32(smraw);
        const unsigned Bs0 = As0 + G8_BUFS * G8_TILE_B;
        const int lane = tid & 31, wid = tid >> 5;
        const int wm = (wid & 3) * 32;
        const int wn = (wid >> 2) * 64;

        const int ldrow = tid >> 1;
        const int ccol  = (tid & 1) * 16;
        const unsigned short* Ag = g_X8 + (size_t)(bx * 128 + ldrow) * 256 + ccol;
        const unsigned short* Bg = g_W8 + (size_t)(by * 128 + ldrow) * 256 + ccol;
        const unsigned soff = (unsigned)(ldrow * G8_ROW + ccol) * 2;

        auto stage = [&](int kt) {
            const unsigned bo = (unsigned)(kt & 3) * G8_TILE_B;
            const unsigned short* sa = Ag + kt * 32;
            const unsigned short* sb = Bg + kt * 32;
            CP_ASYNC16(As0 + bo + soff,      sa);
            CP_ASYNC16(As0 + bo + soff + 16, sa + 8);
            CP_ASYNC16(Bs0 + bo + soff,      sb);
            CP_ASYNC16(Bs0 + bo + soff + 16, sb + 8);
            CP_COMMIT();
        };

        float d[2][8][4];
#pragma unroll
        for (int mi = 0; mi < 2; mi++)
#pragma unroll
            for (int nj = 0; nj < 8; nj++)
#pragma unroll
                for (int q = 0; q < 4; q++) d[mi][nj][q] = 0.0f;

        unsigned aAddr[2], bAddr[4];
#pragma unroll
        for (int mi = 0; mi < 2; mi++)
            aAddr[mi] = As0 + (unsigned)((wm + mi * 16 + (lane & 15)) * G8_ROW + (lane >> 4) * 8) * 2;
#pragma unroll
        for (int np = 0; np < 4; np++) {
            int r = wn + np * 16 + (lane & 7) + ((lane >> 4) & 1) * 8;
            int c = ((lane >> 3) & 1) * 8;
            bAddr[np] = Bs0 + (unsigned)(r * G8_ROW + c) * 2;
        }

        stage(0); stage(1); stage(2);

#pragma unroll
        for (int kt = 0; kt < 8; kt++) {
            CP_WAIT2();
            __syncthreads();
            const unsigned bo = (unsigned)(kt & 3) * G8_TILE_B;
#pragma unroll
            for (int kq = 0; kq < 2; kq++) {
                const unsigned off = bo + kq * 32;
                unsigned ra[2][4], rb[4][4];
#pragma unroll
                for (int mi = 0; mi < 2; mi++) ldmatrix_x4(ra[mi], aAddr[mi] + off);
#pragma unroll
                for (int np = 0; np < 4; np++) ldmatrix_x4(rb[np], bAddr[np] + off);
#pragma unroll
                for (int mi = 0; mi < 2; mi++)
#pragma unroll
                    for (int nj = 0; nj < 8; nj++) {
                        int np = nj >> 1;
                        unsigned b0 = (nj & 1) ? rb[np][2] : rb[np][0];
                        unsigned b1 = (nj & 1) ? rb[np][3] : rb[np][1];
                        mma_fp8(d[mi][nj], ra[mi], b0, b1);
                    }
            }
            if (kt + 3 < 8) stage(kt + 3); else CP_COMMIT();
        }

        const float dsc = INVLN2 * DESCALE;
#pragma unroll
        for (int mi = 0; mi < 2; mi++) {
            float se0 = 0.0f, se1 = 0.0f;
            int r = bx * 128 + wm + mi * 16 + (lane >> 2);
#pragma unroll
            for (int nj = 0; nj < 8; nj++) {
                int c = by * 128 + wn + nj * 8 + (lane & 3) * 2;
                float b0 = __ldg(&bias[c]) * INVLN2;
                float b1 = __ldg(&bias[c + 1]) * INVLN2;
                se0 += ex2f(fmaf(d[mi][nj][0], dsc, b0)) + ex2f(fmaf(d[mi][nj][1], dsc, b1));
                se1 += ex2f(fmaf(d[mi][nj][2], dsc, b0)) + ex2f(fmaf(d[mi][nj][3], dsc, b1));
            }
            se0 += __shfl_xor_sync(0xffffffffu, se0, 1);
            se0 += __shfl_xor_sync(0xffffffffu, se0, 2);
            se1 += __shfl_xor_sync(0xffffffffu, se1, 1);
            se1 += __shfl_xor_sync(0xffffffffu, se1, 2);
            if ((lane & 3) == 0) {
                atomicAdd(&g_sumexp[r], se0);
                atomicAdd(&g_sumexp[r + 8], se1);
            }
        }
        __threadfence();
        __syncthreads();
        if (tid == 0) atomicAdd(&g_cnt[bx], 1);
        return;
    }

    if (blockIdx.x >= 32) {
        // ================= label GEMM role (no lse; no gemm0 dependency) =================
        const int flat = blockIdx.x - 32;
        const int bx = flat >> 5;
        const int by = flat & 31;

        if (bx * 128 >= elens[by]) {
            if (tid == 0) { __threadfence(); atomicExch(&g_done[by * 8 + bx], 1); }
            return;
        }

        const unsigned As0 = smem_u32(smraw);
        const unsigned Bs0 = As0 + G8_BUFS * G8_TILE_B;
        const int lane = tid & 31, wid = tid >> 5;
        const int wm = (wid & 3) * 32;
        const int wn = (wid >> 2) * 64;

        const int ldrow = tid >> 1;
        const int ccol  = (tid & 1) * 16;
        int trow_ld = bx * 128 + ldrow;
        if (trow_ld > TT - 1) trow_ld = TT - 1;
        const unsigned short* Ag = g_X8    + (size_t)(by * TT + trow_ld) * 256 + ccol;
        const unsigned short* Bg = g_Wlab8 + (size_t)(by * 128 + ldrow) * 256 + ccol;
        const unsigned soff = (unsigned)(ldrow * G8_ROW + ccol) * 2;

        auto stage = [&](int kt) {
            const unsigned bo = (unsigned)(kt & 3) * G8_TILE_B;
            const unsigned short* sa = Ag + kt * 32;
            const unsigned short* sb = Bg + kt * 32;
            CP_ASYNC16(As0 + bo + soff,      sa);
            CP_ASYNC16(As0 + bo + soff + 16, sa + 8);
            CP_ASYNC16(Bs0 + bo + soff,      sb);
            CP_ASYNC16(Bs0 + bo + soff + 16, sb + 8);
            CP_COMMIT();
        };

        float d[2][8][4];
#pragma unroll
        for (int mi = 0; mi < 2; mi++)
#pragma unroll
            for (int nj = 0; nj < 8; nj++)
#pragma unroll
                for (int q = 0; q < 4; q++) d[mi][nj][q] = 0.0f;

        unsigned aAddr[2], bAddr[4];
#pragma unroll
        for (int mi = 0; mi < 2; mi++)
            aAddr[mi] = As0 + (unsigned)((wm + mi * 16 + (lane & 15)) * G8_ROW + (lane >> 4) * 8) * 2;
#pragma unroll
        for (int np = 0; np < 4; np++) {
            int r = wn + np * 16 + (lane & 7) + ((lane >> 4) & 1) * 8;
            int c = ((lane >> 3) & 1) * 8;
            bAddr[np] = Bs0 + (unsigned)(r * G8_ROW + c) * 2;
        }

        stage(0); stage(1); stage(2);

#pragma unroll
        for (int kt = 0; kt < 8; kt++) {
            CP_WAIT2();
            __syncthreads();
            const unsigned bo = (unsigned)(kt & 3) * G8_TILE_B;
#pragma unroll
            for (int kq = 0; kq < 2; kq++) {
                const unsigned off = bo + kq * 32;
                unsigned ra[2][4], rb[4][4];
#pragma unroll
                for (int mi = 0; mi < 2; mi++) ldmatrix_x4(ra[mi], aAddr[mi] + off);
#pragma unroll
                for (int np = 0; np < 4; np++) ldmatrix_x4(rb[np], bAddr[np] + off);
#pragma unroll
                for (int mi = 0; mi < 2; mi++)
#pragma unroll
                    for (int nj = 0; nj < 8; nj++) {
                        int np = nj >> 1;
                        unsigned b0 = (nj & 1) ? rb[np][2] : rb[np][0];
                        unsigned b1 = (nj & 1) ? rb[np][3] : rb[np][1];
                        mma_fp8(d[mi][nj], ra[mi], b0, b1);
                    }
            }
            if (kt + 3 < 8) stage(kt + 3); else CP_COMMIT();
        }

        // store lp2' = (d/64 + blab) / ln2    (lse applied by DP)
#pragma unroll
        for (int mi = 0; mi < 2; mi++) {
            int trow = bx * 128 + wm + mi * 16 + (lane >> 2);
#pragma unroll
            for (int nj = 0; nj < 8; nj++) {
                int c = wn + nj * 8 + (lane & 3) * 2;
                float bl0 = g_blab[by * 128 + c];
                float bl1 = g_blab[by * 128 + c + 1];
                if (trow < TT) {
                    float2 v = make_float2(
                        fmaf(d[mi][nj][0], DESCALE, bl0) * INVLN2,
                        fmaf(d[mi][nj][1], DESCALE, bl1) * INVLN2);
                    *(float2*)&g_lab[(size_t)(by * TT + trow) * 128 + c] = v;
                }
                if (trow + 8 < TT) {
                    float2 v = make_float2(
                        fmaf(d[mi][nj][2], DESCALE, bl0) * INVLN2,
                        fmaf(d[mi][nj][3], DESCALE, bl1) * INVLN2);
                    *(float2*)&g_lab[(size_t)(by * TT + trow + 8) * 128 + c] = v;
                }
            }
        }
        __threadfence();
        __syncthreads();
        if (tid == 0) atomicExch(&g_done[by * 8 + bx], 1);
        return;
    }

    // ================= CTC DP role (8 warps, halo 4, 1 dstep per commit) =================
    const int b    = blockIdx.x;
    const int lane = tid & 31;
    const int w    = tid >> 5;              // 0..7
    const int s    = w * 28 + lane - 4;     // -4..223

    float* Asd = (float*)smraw;                       // [2][224]
    float* qb  = (float*)(smraw + 1792);              // [2][24][128]
    float* lsb = (float*)(smraw + 1792 + 24576);      // [2][24]
    const unsigned qb0 = smem_u32(smraw) + 1792;

    const int ylen = ylens[b];
    const int tend = elens[b] - 1;

    const bool in_s  = (s >= 0 && s <= 200);
    const bool valid = in_s && (s <= 2 * ylen);

    const int sc0 = min(max(s, 0), 200);
    const int li0 = (sc0 & 1) ? ((sc0 >> 1) + 1) : 0;

    auto skip_of = [&](int x) -> float {
        if ((x & 1) && x >= 3 && x <= 200) {
            int h = x >> 1;
            return (ys[b * LL + h] != ys[b * LL + h - 1]) ? 1.0f : 0.0f;
        }
        return 0.0f;
    };
    const float sk0 = skip_of(s);
    const float sk1 = skip_of(s - 1);
    const float sk2 = skip_of(s - 2);
    const bool use3 = (sk0 != 0.0f) || (sk1 != 0.0f);
    const bool use4 = (sk0 != 0.0f) && (sk2 != 0.0f);

    // dependency waiter: tid0 spins (nanosleep backoff), block barriers after
    volatile int* dn1 = (volatile int*)(g_done + b * 8);
    volatile int* cnt = (volatile int*)g_cnt;
    int rdy1 = 0;
    int rdym = (b * TT) >> 7;
    auto waitDeps = [&](int tl) {
        if (tid == 0) {
            int tile1 = tl >> 7;
            int m0 = (b * TT + tl) >> 7;
            while (rdy1 <= tile1) { if (dn1[rdy1] != 0) rdy1++; else __nanosleep(128); }
            while (rdym <= m0)    { if (cnt[rdym] >= 16) rdym++; else __nanosleep(128); }
        }
        __syncthreads();
        __threadfence();
    };

    float pendA = 1.0f, pendB = 1.0f;

    auto stage = [&](int cc, int bf) {
        int t0 = 1 + cc * 24;
        int tl = min(t0 + 23, TT - 1);
        waitDeps(tl);
        const float4* src = (const float4*)(g_lab + (size_t)(b * TT + t0) * 128);
        unsigned dst = qb0 + (unsigned)bf * 12288u;
        for (int idx = tid; idx < 768; idx += 256)
            CP_ASYNC16(dst + (unsigned)idx * 16u, src + idx);
        CP_COMMIT();
        if (tid < 24) {
            float v = __ldcg(&g_sumexp[b * TT + t0 + tid]);   // .cg: L2-coherent
            if (bf) pendB = v; else pendA = v;
        }
    };

    // t = 0 init
    waitDeps(0);
    float ls0 = lg2f(__ldcg(&g_sumexp[b * TT]));
    float a = NEG_INF;
    if (valid && s < 2) a = g_lab[(size_t)(b * TT) * 128 + li0] - ls0;

    auto dstep = [&](int f0, int bf) {
        float a1 = __shfl_up_sync(0xffffffffu, a, 1);
        float a2 = __shfl_up_sync(0xffffffffu, a, 2);
        float a3 = __shfl_up_sync(0xffffffffu, a, 3);
        float a4 = __shfl_up_sync(0xffffffffu, a, 4);
        float a3u = use3 ? a3 : NEG_INF;
        float a4u = use4 ? a4 : NEG_INF;
        float lpA = qb[(bf * 24 + f0) * 128 + li0] - lsb[bf * 24 + f0];
        float lpB = qb[(bf * 24 + f0 + 1) * 128 + li0] - lsb[bf * 24 + f0 + 1];
        float P0 = ex2f(lpA);
        float P1 = __shfl_up_sync(0xffffffffu, P0, 1);
        float P2 = __shfl_up_sync(0xffffffffu, P0, 2);
        float m  = fmaxf(fmaxf(a, a1), fmaxf(fmaxf(a2, a3u), a4u));
        float q0 = ex2f(a - m),  q1 = ex2f(a1 - m), q2 = ex2f(a2 - m);
        float q3 = ex2f(a3u - m), q4 = ex2f(a4u - m);
        float I0 = fmaf(sk0, q2, q0 + q1);
        float I1 = fmaf(sk1, q3, q1 + q2);
        float I2 = fmaf(sk2, q4, q2 + q3);
        float S  = fmaf(P0, I0, fmaf(P1, I1, sk0 * P2 * I2));
        float nv = fmaxf(m + lg2f(S) + lpB, NEG_INF);
        a = valid ? nv : NEG_INF;
    };

    auto sstep = [&](int f0, int bf) {
        float a1 = __shfl_up_sync(0xffffffffu, a, 1);
        float a2 = __shfl_up_sync(0xffffffffu, a, 2);
        if (sk0 == 0.0f) a2 = NEG_INF;
        float lp = qb[(bf * 24 + f0) * 128 + li0] - lsb[bf * 24 + f0];
        float m  = fmaxf(a, fmaxf(a1, a2));
        float su = ex2f(a - m) + ex2f(a1 - m) + ex2f(a2 - m);
        float nv = fmaxf(m + lg2f(su) + lp, NEG_INF);
        a = valid ? nv : NEG_INF;
    };

    stage(0, 0);
    stage(1, 1);

    int wb = 0, lastwb = 0;
    int t = 1, c = 0;
    while (t <= tend) {
        CP_WAIT1();
        __syncthreads();
        const int bf = c & 1;
        if (tid < 24) lsb[bf * 24 + tid] = lg2f(bf ? pendB : pendA);
        __syncthreads();
        const int nfr = min(24, tend - t + 1);
        int fr = 0;
        while (fr < nfr) {
            int rem = nfr - fr;
            int h;
            if (rem >= 2) { dstep(fr, bf); h = 4; fr += 2; }
            else          { sstep(fr, bf); h = 2; fr += 1; }
            if (lane >= h && in_s) Asd[wb * 224 + s] = a;
            __syncthreads();
            a = in_s ? Asd[wb * 224 + s] : NEG_INF;
            lastwb = wb; wb ^= 1;
        }
        if (nfr == 24) stage(c + 2, bf);
        t += nfr; c++;
    }

    if (tid == 0) {
        float last = Asd[lastwb * 224 + 2 * ylen];
        float prev = Asd[lastwb * 224 + 2 * ylen - 1];
        float mm = fmaxf(last, prev);
        float l2v = mm + lg2f(ex2f(last - mm) + ex2f(prev - mm));
        float lnat = -l2v * LN2;
        if (!(lnat < -0.5f * NEG_INF)) lnat = 0.0f;   // zero_infinity
        atomicAdd(out, lnat * (1.0f / (float)BB));
    }
}

// ---------------- launch ----------------
extern "C" void kernel_launch(void* const* d_in, const int* in_sizes, int n_in,
                              void* d_out, int out_size) {
    const float* eouts = (const float*)d_in[0];
    const float* W     = (const float*)d_in[1];
    const float* bias  = (const float*)d_in[2];
    const int*   ys    = (const int*)d_in[3];
    const int*   elens = (const int*)d_in[4];
    const int*   ylens = (const int*)d_in[5];
    float* out = (float*)d_out;

    cudaFuncSetAttribute(fused_kernel,
                         cudaFuncAttributeMaxDynamicSharedMemorySize, G8_SMEM);

    prep_kernel<<<2048, 256>>>(eouts, W, bias, ys, elens, out, out_size);
    fused_kernel<<<4288, 256, G8_SMEM>>>(bias, ys, elens, ylens, out);
}